// round 16
// baseline (speedup 1.0000x reference)
#include <cuda_runtime.h>
#include <cuda_bf16.h>

#define NG   768
#define H    128
#define PAD  132   // smem row stride in floats; 16B-aligned; PAD%32==4 -> conflict-free col access

typedef unsigned long long u64;

// Scratch: columns [0:128)=Ai, [128:256)=Bjb (=Bj+b1), [256:384)=Q (=Wb·x_j rows)
__device__ float g_pre[NG * 384];
// W2 logit-difference vectors: [0:128)=W2[0]-W2[1], [128:256)=W2[1]-W2[2]
__device__ float g_wd[256];

// ------------------------- packed f32x2 helpers ----------------------------
union F2U { u64 u; float2 f; };

__device__ __forceinline__ u64 pk2(float lo, float hi) {
    F2U t; t.f = make_float2(lo, hi); return t.u;
}
__device__ __forceinline__ float2 upk2(u64 v) {
    F2U t; t.u = v; return t.f;
}
__device__ __forceinline__ u64 addx2(u64 a, u64 b) {
    u64 r;
    asm("add.rn.f32x2 %0, %1, %2;" : "=l"(r) : "l"(a), "l"(b));
    return r;
}
__device__ __forceinline__ u64 fmax2(u64 a, u64 b, u64 c) {
    u64 r;
    asm("fma.rn.f32x2 %0, %1, %2, %3;" : "=l"(r) : "l"(a), "l"(b), "l"(c));
    return r;
}
__device__ __forceinline__ u64 relux2(u64 s) {
    F2U t; t.u = s;
    t.f.x = fmaxf(t.f.x, 0.f);   // FMNMX on alu pipe, overlaps fma pipe
    t.f.y = fmaxf(t.f.y, 0.f);
    return t.u;
}

// ---------------------------------------------------------------------------
// Kernel 1: per-gene projections as one 768x384x128 GEMM (packed f32x2).
// 16x32 tile, 128 threads, 2x2 micro-tile, grid=576 (~4 blocks/SM).
// Output column kk: kk<128 -> Ai, kk<256 -> Bjb (+b1), kk<384 -> Q.
// Block (0,0) additionally writes the W2 logit-diff vectors to g_wd.
// ---------------------------------------------------------------------------
__global__ __launch_bounds__(128) void prep_kernel(
    const float* __restrict__ X, const float* __restrict__ W1,
    const float* __restrict__ b1, const float* __restrict__ Wb,
    const float* __restrict__ W2)
{
    extern __shared__ float sm[];
    float* Xs = sm;              // 16 rows x PAD
    float* Ws = sm + 16 * PAD;   // 32 rows x PAD

    const int i0 = blockIdx.y * 16;
    const int c0 = blockIdx.x * 32;
    const int tid = threadIdx.x;

    if (blockIdx.x == 0 && blockIdx.y == 0) {
        g_wd[tid]       = W2[tid]       - W2[128 + tid];
        g_wd[128 + tid] = W2[128 + tid] - W2[256 + tid];
    }

    for (int q = tid; q < 512; q += 128) {
        int r = q >> 5, mq = q & 31;
        *(float4*)(Xs + r * PAD + mq * 4) =
            *(const float4*)(X + (i0 + r) * H + mq * 4);
    }
    for (int q = tid; q < 1024; q += 128) {
        int r = q >> 5, mq = q & 31;
        int kk = c0 + r;
        const float* rp;
        if (kk < 128)      rp = W1 + kk * 256;
        else if (kk < 256) rp = W1 + (kk - 128) * 256 + 128;
        else               rp = Wb + (kk - 256) * 128;
        *(float4*)(Ws + r * PAD + mq * 4) = *(const float4*)(rp + mq * 4);
    }
    __syncthreads();

    const int t16 = tid & 15;
    const int rl  = (tid >> 4) * 2;

    u64 acc[4];
#pragma unroll
    for (int p = 0; p < 4; p++) acc[p] = 0ull;

#pragma unroll 2
    for (int m0 = 0; m0 < 128; m0 += 4) {
        ulonglong2 xr[2], wc[2];
#pragma unroll
        for (int r = 0; r < 2; r++)
            xr[r] = *(const ulonglong2*)(Xs + (rl + r) * PAD + m0);
        wc[0] = *(const ulonglong2*)(Ws + t16 * PAD + m0);
        wc[1] = *(const ulonglong2*)(Ws + (t16 + 16) * PAD + m0);

#pragma unroll
        for (int h = 0; h < 2; h++)
#pragma unroll
            for (int r = 0; r < 2; r++) {
                const u64 xh = h ? xr[r].y : xr[r].x;
#pragma unroll
                for (int c = 0; c < 2; c++) {
                    const u64 wh = h ? wc[c].y : wc[c].x;
                    acc[r * 2 + c] = fmax2(xh, wh, acc[r * 2 + c]);
                }
            }
    }

#pragma unroll
    for (int r = 0; r < 2; r++)
#pragma unroll
        for (int c = 0; c < 2; c++) {
            const int kk = c0 + t16 + c * 16;
            float2 s = upk2(acc[r * 2 + c]);
            float v = s.x + s.y;
            if (kk >= 128 && kk < 256) v += b1[kk - 128];
            g_pre[(i0 + rl + r) * 384 + kk] = v;
        }
}

// ---------------------------------------------------------------------------
// Kernel 2: fused pairwise MLP + argmax + bilinear sign-combine.
// 64x64 tile, 512 threads, 4x2 micro-tile (rows il..il+3, cols {tx, tx+32}).
// J-side (Bjb, Q) in smem; I-side (Ai, X) and weights via UNIFORM LDG
// (warp-uniform address -> 1 l1tex wavefront instead of 4 crossbar cycles,
//  data L1-resident: 4KB/warp). Crossbar ~13.3K cyc/SM < fma floor 16.4K.
// Logit diffs: u = l0-l1, w = l1-l2.
// ---------------------------------------------------------------------------
__global__ __launch_bounds__(512) void pair_kernel(
    const float* __restrict__ X, const float* __restrict__ b2,
    const float* __restrict__ bb, float* __restrict__ out)
{
    extern __shared__ float sm[];
    float* Bs = sm;              // Bjb rows (j-side), 64 x PAD
    float* Qs = sm + 64 * PAD;   // Q   rows (j-side), 64 x PAD

    const int i0 = blockIdx.y * 64;
    const int j0 = blockIdx.x * 64;
    const int tid = threadIdx.x;

    for (int q = tid; q < 2048; q += 512) {
        int r = q >> 5, mq = q & 31;
        *(float4*)(Bs + r * PAD + mq * 4) =
            *(const float4*)(g_pre + (j0 + r) * 384 + 128 + mq * 4);
        *(float4*)(Qs + r * PAD + mq * 4) =
            *(const float4*)(g_pre + (j0 + r) * 384 + 256 + mq * 4);
    }
    __syncthreads();

    const float u0  = b2[0] - b2[1];
    const float w0  = b2[1] - b2[2];
    const float bb0 = bb[0];

    const int tx = tid & 31, ty = tid >> 5;
    const int il = ty * 4;   // rows il..il+3; cols {tx, tx+32}

    // Warp-uniform i-side base pointers (Ai rows in g_pre, X rows in gmem).
    const float* __restrict__ aP[4];
    const float* __restrict__ xP[4];
#pragma unroll
    for (int r = 0; r < 4; r++) {
        aP[r] = g_pre + (i0 + il + r) * 384;   // Ai columns [0:128)
        xP[r] = X + (i0 + il + r) * H;
    }

    u64 u[8], w[8], af[8];
#pragma unroll
    for (int p = 0; p < 8; p++) {
        u[p]  = pk2(u0, 0.f);
        w[p]  = pk2(w0, 0.f);
        af[p] = pk2(bb0, 0.f);
    }

#pragma unroll 2
    for (int k0 = 0; k0 < 128; k0 += 4) {
        ulonglong2 a2[4], x2[4], bv[2], qv[2];
#pragma unroll
        for (int r = 0; r < 4; r++) {
            a2[r] = *(const ulonglong2*)(aP[r] + k0);   // uniform LDG.128
            x2[r] = *(const ulonglong2*)(xP[r] + k0);   // uniform LDG.128
        }
        bv[0] = *(const ulonglong2*)(Bs + tx * PAD + k0);
        bv[1] = *(const ulonglong2*)(Bs + (tx + 32) * PAD + k0);
        qv[0] = *(const ulonglong2*)(Qs + tx * PAD + k0);
        qv[1] = *(const ulonglong2*)(Qs + (tx + 32) * PAD + k0);
        const ulonglong2 wu2 = *(const ulonglong2*)(g_wd + k0);        // uniform LDG
        const ulonglong2 wv2 = *(const ulonglong2*)(g_wd + 128 + k0);  // uniform LDG

#pragma unroll
        for (int h = 0; h < 2; h++) {
            const u64 wuh = h ? wu2.y : wu2.x;
            const u64 wvh = h ? wv2.y : wv2.x;
#pragma unroll
            for (int r = 0; r < 4; r++) {
                const u64 ah = h ? a2[r].y : a2[r].x;
                const u64 xh = h ? x2[r].y : x2[r].x;
#pragma unroll
                for (int c = 0; c < 2; c++) {
                    const int p = r * 2 + c;
                    const u64 bh = h ? bv[c].y : bv[c].x;
                    const u64 qh = h ? qv[c].y : qv[c].x;
                    const u64 t = relux2(addx2(ah, bh));
                    u[p]  = fmax2(t, wuh, u[p]);
                    w[p]  = fmax2(t, wvh, w[p]);
                    af[p] = fmax2(xh, qh, af[p]);
                }
            }
        }
    }

#pragma unroll
    for (int r = 0; r < 4; r++) {
        const int i = i0 + il + r;
#pragma unroll
        for (int c = 0; c < 2; c++) {
            const int p = r * 2 + c;
            const int j = j0 + tx + c * 32;
            float2 s;
            s = upk2(u[p]);  const float us = s.x + s.y;
            s = upk2(w[p]);  const float ws = s.x + s.y;
            s = upk2(af[p]); const float as = s.x + s.y;
            // first-max argmax on differences:
            // is0: l0>=l1 (u>=0) && l0>=l2 (u+w>=0); is2: !is0 && l2>l1 (w<0)
            const bool is0 = (us >= 0.f) && (us + ws >= 0.f);
            const bool is2 = !is0 && (ws < 0.f);
            float v = is0 ? as : (is2 ? -as : 0.f);
            if (i == j) v = 0.f;
            out[i * NG + j] = v;
        }
    }
}

extern "C" void kernel_launch(void* const* d_in, const int* in_sizes, int n_in,
                              void* d_out, int out_size)
{
    const float* X  = (const float*)d_in[0];  // [768,128]
    const float* W1 = (const float*)d_in[1];  // [128,256]
    const float* b1 = (const float*)d_in[2];  // [128]
    const float* W2 = (const float*)d_in[3];  // [3,128]
    const float* b2 = (const float*)d_in[4];  // [3]
    const float* Wb = (const float*)d_in[5];  // [1,128,128]
    const float* bb = (const float*)d_in[6];  // [1]
    float* out = (float*)d_out;

    const int smemP = (16 + 32) * PAD * (int)sizeof(float);   // 25344 B
    const int smemB = 2 * 64 * PAD * (int)sizeof(float);      // 67584 B
    cudaFuncSetAttribute(prep_kernel, cudaFuncAttributeMaxDynamicSharedMemorySize, smemP);
    cudaFuncSetAttribute(pair_kernel, cudaFuncAttributeMaxDynamicSharedMemorySize, smemB);

    prep_kernel<<<dim3(12, 48), 128, smemP>>>(X, W1, b1, Wb, W2);
    pair_kernel<<<dim3(12, 12), 512, smemB>>>(X, b2, bb, out);
}

// round 17
// speedup vs baseline: 1.1537x; 1.1537x over previous
#include <cuda_runtime.h>
#include <cuda_bf16.h>

#define NG        768
#define H         128
#define PAD       132   // smem row stride in floats; PAD%32==4 -> conflict-free col access
#define GRID_BLKS 144u

typedef unsigned long long u64;

// Scratch: columns [0:128)=Ai, [128:256)=Bjb (=Bj+b1), [256:384)=Q (=Wb·x_j rows)
__device__ float g_pre[NG * 384];
// Monotonic global-barrier ticket counter (never reset; wraps after ~30M launches)
__device__ unsigned g_bar = 0;

// ------------------------- packed f32x2 helpers ----------------------------
union F2U { u64 u; float2 f; };

__device__ __forceinline__ u64 pk2(float lo, float hi) {
    F2U t; t.f = make_float2(lo, hi); return t.u;
}
__device__ __forceinline__ float2 upk2(u64 v) {
    F2U t; t.u = v; return t.f;
}
__device__ __forceinline__ u64 addx2(u64 a, u64 b) {
    u64 r;
    asm("add.rn.f32x2 %0, %1, %2;" : "=l"(r) : "l"(a), "l"(b));
    return r;
}
__device__ __forceinline__ u64 fmax2(u64 a, u64 b, u64 c) {
    u64 r;
    asm("fma.rn.f32x2 %0, %1, %2, %3;" : "=l"(r) : "l"(a), "l"(b), "l"(c));
    return r;
}
__device__ __forceinline__ u64 relux2(u64 s) {
    F2U t; t.u = s;
    t.f.x = fmaxf(t.f.x, 0.f);
    t.f.y = fmaxf(t.f.y, 0.f);
    return t.u;
}

// ---------------------------------------------------------------------------
// ONE persistent kernel, grid 12x12 (144 blocks, 1/SM, all co-resident).
// Phase 1: each block computes a 64x32 slice of g_pre (768x384x128 GEMM).
// Global spin barrier (monotonic ticket; deterministic; graph-replay-safe).
// Phase 2: fused pairwise MLP + argmax + bilinear sign-combine (R8 body):
//   64x64 tile, 512 threads, 4x2 micro-tile, packed f32x2 along k.
// ---------------------------------------------------------------------------
__global__ __launch_bounds__(512) void fused_kernel(
    const float* __restrict__ X,  const float* __restrict__ W1,
    const float* __restrict__ b1, const float* __restrict__ Wb,
    const float* __restrict__ W2, const float* __restrict__ b2,
    const float* __restrict__ bb, float* __restrict__ out)
{
    extern __shared__ float sm[];
    const int tid = threadIdx.x;

    // ======================= Phase 1: prep slice ==========================
    {
        float* Xs = sm;              // 64 rows x PAD (X rows i0..i0+63)
        float* Ws = sm + 64 * PAD;   // 32 rows x PAD (weight rows for out-cols)
        const int i0 = blockIdx.y * 64;   // 12 * 64 = 768 rows
        const int c0 = blockIdx.x * 32;   // 12 * 32 = 384 cols

        for (int q = tid; q < 2048; q += 512) {         // 64 rows x 32 float4
            int r = q >> 5, mq = q & 31;
            *(float4*)(Xs + r * PAD + mq * 4) =
                *(const float4*)(X + (i0 + r) * H + mq * 4);
        }
        for (int q = tid; q < 1024; q += 512) {         // 32 rows x 32 float4
            int r = q >> 5, mq = q & 31;
            int kk = c0 + r;
            const float* rp;
            if (kk < 128)      rp = W1 + kk * 256;
            else if (kk < 256) rp = W1 + (kk - 128) * 256 + 128;
            else               rp = Wb + (kk - 256) * 128;
            *(float4*)(Ws + r * PAD + mq * 4) = *(const float4*)(rp + mq * 4);
        }
        __syncthreads();

        const int tx = tid & 15;     // cols {c0+tx, c0+tx+16}
        const int ty = tid >> 4;     // [0,32): rows {2ty, 2ty+1}
        const int rl = ty * 2;

        u64 acc[4];
#pragma unroll
        for (int p = 0; p < 4; p++) acc[p] = 0ull;

#pragma unroll 2
        for (int m0 = 0; m0 < 128; m0 += 4) {
            ulonglong2 xr[2], wc[2];
#pragma unroll
            for (int r = 0; r < 2; r++)
                xr[r] = *(const ulonglong2*)(Xs + (rl + r) * PAD + m0);
            wc[0] = *(const ulonglong2*)(Ws + tx * PAD + m0);
            wc[1] = *(const ulonglong2*)(Ws + (tx + 16) * PAD + m0);

#pragma unroll
            for (int h = 0; h < 2; h++)
#pragma unroll
                for (int r = 0; r < 2; r++) {
                    const u64 xh = h ? xr[r].y : xr[r].x;
#pragma unroll
                    for (int c = 0; c < 2; c++) {
                        const u64 wh = h ? wc[c].y : wc[c].x;
                        acc[r * 2 + c] = fmax2(xh, wh, acc[r * 2 + c]);
                    }
                }
        }

#pragma unroll
        for (int r = 0; r < 2; r++)
#pragma unroll
            for (int c = 0; c < 2; c++) {
                const int kk = c0 + tx + c * 16;
                float2 s = upk2(acc[r * 2 + c]);
                float v = s.x + s.y;
                if (kk >= 128 && kk < 256) v += b1[kk - 128];
                g_pre[(i0 + rl + r) * 384 + kk] = v;
            }
    }

    // ===================== global barrier (all 144 resident) ==============
    __threadfence();     // each thread's g_pre stores visible device-wide
    __syncthreads();     // whole block done before arrival
    if (tid == 0) {
        unsigned t = atomicAdd(&g_bar, 1u);
        unsigned base = t - (t % GRID_BLKS);
        while (atomicAdd(&g_bar, 0u) < base + GRID_BLKS) __nanosleep(64);
        __threadfence();
    }
    __syncthreads();

    // ======================= Phase 2: pair loop (R8 body) =================
    float* As  = sm;                 // Ai  rows (i-side)
    float* Xi  = sm + 64 * PAD;      // X   rows (i-side)
    float* Bs  = sm + 2 * 64 * PAD;  // Bjb rows (j-side)
    float* Qs  = sm + 3 * 64 * PAD;  // Q   rows (j-side)
    float* wus = sm + 4 * 64 * PAD;        // W2[0]-W2[1]
    float* wvs = sm + 4 * 64 * PAD + PAD;  // W2[1]-W2[2]

    const int i0 = blockIdx.y * 64;
    const int j0 = blockIdx.x * 64;

    for (int q = tid; q < 2048; q += 512) {
        int r = q >> 5, mq = q & 31;
        *(float4*)(As + r * PAD + mq * 4) = *(const float4*)(g_pre + (i0 + r) * 384 + mq * 4);
        *(float4*)(Xi + r * PAD + mq * 4) = *(const float4*)(X + (i0 + r) * H + mq * 4);
        *(float4*)(Bs + r * PAD + mq * 4) = *(const float4*)(g_pre + (j0 + r) * 384 + 128 + mq * 4);
        *(float4*)(Qs + r * PAD + mq * 4) = *(const float4*)(g_pre + (j0 + r) * 384 + 256 + mq * 4);
    }
    if (tid < 128) {
        wus[tid] = W2[tid]       - W2[128 + tid];
        wvs[tid] = W2[128 + tid] - W2[256 + tid];
    }
    __syncthreads();

    const float u0  = b2[0] - b2[1];
    const float w0  = b2[1] - b2[2];
    const float bb0 = bb[0];

    const int tx = tid & 31, ty = tid >> 5;
    const int il = ty * 4;   // rows il..il+3; cols {tx, tx+32}

    u64 u[8], w[8], af[8];
#pragma unroll
    for (int p = 0; p < 8; p++) {
        u[p]  = pk2(u0, 0.f);
        w[p]  = pk2(w0, 0.f);
        af[p] = pk2(bb0, 0.f);
    }

#pragma unroll 1
    for (int k0 = 0; k0 < 128; k0 += 4) {
        ulonglong2 a2[4], x2[4], bv[2], qv[2];
#pragma unroll
        for (int r = 0; r < 4; r++) {
            a2[r] = *(const ulonglong2*)(As + (il + r) * PAD + k0);
            x2[r] = *(const ulonglong2*)(Xi + (il + r) * PAD + k0);
        }
        bv[0] = *(const ulonglong2*)(Bs + tx * PAD + k0);
        bv[1] = *(const ulonglong2*)(Bs + (tx + 32) * PAD + k0);
        qv[0] = *(const ulonglong2*)(Qs + tx * PAD + k0);
        qv[1] = *(const ulonglong2*)(Qs + (tx + 32) * PAD + k0);
        const ulonglong2 wu2 = *(const ulonglong2*)(wus + k0);
        const ulonglong2 wv2 = *(const ulonglong2*)(wvs + k0);

#pragma unroll
        for (int h = 0; h < 2; h++) {
            const u64 wuh = h ? wu2.y : wu2.x;
            const u64 wvh = h ? wv2.y : wv2.x;
#pragma unroll
            for (int r = 0; r < 4; r++) {
                const u64 ah = h ? a2[r].y : a2[r].x;
                const u64 xh = h ? x2[r].y : x2[r].x;
#pragma unroll
                for (int c = 0; c < 2; c++) {
                    const int p = r * 2 + c;
                    const u64 bh = h ? bv[c].y : bv[c].x;
                    const u64 qh = h ? qv[c].y : qv[c].x;
                    const u64 t = relux2(addx2(ah, bh));
                    u[p]  = fmax2(t, wuh, u[p]);
                    w[p]  = fmax2(t, wvh, w[p]);
                    af[p] = fmax2(xh, qh, af[p]);
                }
            }
        }
    }

#pragma unroll
    for (int r = 0; r < 4; r++) {
        const int i = i0 + il + r;
#pragma unroll
        for (int c = 0; c < 2; c++) {
            const int p = r * 2 + c;
            const int j = j0 + tx + c * 32;
            float2 s;
            s = upk2(u[p]);  const float us = s.x + s.y;
            s = upk2(w[p]);  const float ws = s.x + s.y;
            s = upk2(af[p]); const float as = s.x + s.y;
            // first-max argmax on differences:
            // is0: l0>=l1 (u>=0) && l0>=l2 (u+w>=0); is2: !is0 && l2>l1 (w<0)
            const bool is0 = (us >= 0.f) && (us + ws >= 0.f);
            const bool is2 = !is0 && (ws < 0.f);
            float v = is0 ? as : (is2 ? -as : 0.f);
            if (i == j) v = 0.f;
            out[i * NG + j] = v;
        }
    }
}

extern "C" void kernel_launch(void* const* d_in, const int* in_sizes, int n_in,
                              void* d_out, int out_size)
{
    const float* X  = (const float*)d_in[0];  // [768,128]
    const float* W1 = (const float*)d_in[1];  // [128,256]
    const float* b1 = (const float*)d_in[2];  // [128]
    const float* W2 = (const float*)d_in[3];  // [3,128]
    const float* b2 = (const float*)d_in[4];  // [3]
    const float* Wb = (const float*)d_in[5];  // [1,128,128]
    const float* bb = (const float*)d_in[6];  // [1]
    float* out = (float*)d_out;

    const int smemB = (4 * 64 * PAD + 2 * PAD) * (int)sizeof(float);   // 136224 B
    cudaFuncSetAttribute(fused_kernel, cudaFuncAttributeMaxDynamicSharedMemorySize, smemB);

    fused_kernel<<<dim3(12, 12), 512, smemB>>>(X, W1, b1, Wb, W2, b2, bb, out);
}